// round 2
// baseline (speedup 1.0000x reference)
#include <cuda_runtime.h>
#include <cstdint>
#include <math_constants.h>

#define A_NUM 9
#define H_DIM 128
#define W_DIM 192
#define NTOT (H_DIM*W_DIM*A_NUM)   // 221184
#define PRE_NMS 6000
#define POST_NMS 300
#define NBINS 4096
#define CAND_CAP 8192
#define VWORDS 192                  // 6144 bits >= PRE_NMS
#define NMS_THR 0.7f

__constant__ float c_anchors[A_NUM][4] = {
    {-84.f,  -40.f,  99.f,  55.f},
    {-176.f, -88.f,  191.f, 103.f},
    {-360.f, -184.f, 375.f, 199.f},
    {-56.f,  -56.f,  71.f,  71.f},
    {-120.f, -120.f, 135.f, 135.f},
    {-248.f, -248.f, 263.f, 263.f},
    {-36.f,  -80.f,  51.f,  95.f},
    {-80.f,  -168.f, 95.f,  183.f},
    {-168.f, -344.f, 183.f, 359.f}};

__device__ float4 g_boxes[NTOT];
__device__ float  g_scores[NTOT];
__device__ int    g_hist[NBINS];
__device__ int    g_thr;
__device__ int    g_numCand;
__device__ unsigned long long g_candKeys[CAND_CAP];
__device__ unsigned long long g_sortedKeys[PRE_NMS];
__device__ float4 g_boxesS[PRE_NMS];
__device__ unsigned int g_validbits[VWORDS];

// ---------------------------------------------------------------- zero scratch
__global__ void k_zero() {
    int i = blockIdx.x * blockDim.x + threadIdx.x;
    if (i < NBINS) g_hist[i] = 0;
    if (i < PRE_NMS) g_sortedKeys[i] = 0ULL;
    if (i == 0) g_numCand = 0;
}

// ---------------------------------------------------------------- box decode + histogram
__global__ void k_prep(const float* __restrict__ scores,
                       const float* __restrict__ deltas,
                       const float* __restrict__ im_info) {
    int i = blockIdx.x * blockDim.x + threadIdx.x;
    if (i >= NTOT) return;
    int a = i % A_NUM;
    int pix = i / A_NUM;
    int x = pix % W_DIM;
    int y = pix / W_DIM;
    const int HW = H_DIM * W_DIM;
    int p = y * W_DIM + x;

    float sc = scores[(A_NUM + a) * HW + p];
    float dx = deltas[(4 * a + 0) * HW + p];
    float dy = deltas[(4 * a + 1) * HW + p];
    float dw = deltas[(4 * a + 2) * HW + p];
    float dh = deltas[(4 * a + 3) * HW + p];
    dw = fminf(fmaxf(dw, -10.f), 10.f);
    dh = fminf(fmaxf(dh, -10.f), 10.f);

    float sx = (float)x * 16.f;
    float sy = (float)y * 16.f;
    float ax1 = c_anchors[a][0] + sx;
    float ay1 = c_anchors[a][1] + sy;
    float ax2 = c_anchors[a][2] + sx;
    float ay2 = c_anchors[a][3] + sy;
    float wdt = ax2 - ax1 + 1.f;
    float hgt = ay2 - ay1 + 1.f;
    float cx = ax1 + 0.5f * wdt;
    float cy = ay1 + 0.5f * hgt;

    float pcx = dx * wdt + cx;
    float pcy = dy * hgt + cy;
    float pw = expf(dw) * wdt;
    float ph = expf(dh) * hgt;

    float imH = im_info[0], imW = im_info[1], sc_im = im_info[2];
    float x1 = pcx - 0.5f * pw;
    float y1 = pcy - 0.5f * ph;
    float x2 = pcx + 0.5f * pw;
    float y2 = pcy + 0.5f * ph;
    x1 = fminf(fmaxf(x1, 0.f), imW - 1.f);
    x2 = fminf(fmaxf(x2, 0.f), imW - 1.f);
    y1 = fminf(fmaxf(y1, 0.f), imH - 1.f);
    y2 = fminf(fmaxf(y2, 0.f), imH - 1.f);

    g_boxes[i] = make_float4(x1, y1, x2, y2);
    float minsz = 16.f * sc_im;
    bool valid = (x2 - x1 + 1.f >= minsz) && (y2 - y1 + 1.f >= minsz);
    g_scores[i] = valid ? sc : -CUDART_INF_F;
    if (valid) {
        int bin = (int)(sc * (float)NBINS);
        bin = max(0, min(NBINS - 1, bin));
        atomicAdd(&g_hist[bin], 1);
    }
}

// ---------------------------------------------------------------- histogram threshold
__global__ void k_thresh() {
    __shared__ int sh[NBINS];
    for (int b = threadIdx.x; b < NBINS; b += blockDim.x) sh[b] = g_hist[b];
    __syncthreads();
    if (threadIdx.x == 0) {
        int cum = 0, thr = 0;
        for (int b = NBINS - 1; b >= 0; b--) {
            cum += sh[b];
            if (cum >= PRE_NMS) { thr = b; break; }
        }
        g_thr = thr;
    }
}

// ---------------------------------------------------------------- candidate compaction
__global__ void k_filter() {
    int i = blockIdx.x * blockDim.x + threadIdx.x;
    if (i >= NTOT) return;
    float s = g_scores[i];
    if (!(s >= 0.0f)) return;   // invalid -> -inf
    int bin = (int)(s * (float)NBINS);
    bin = max(0, min(NBINS - 1, bin));
    if (bin < g_thr) return;
    int p = atomicAdd(&g_numCand, 1);
    if (p < CAND_CAP) {
        unsigned long long key =
            ((unsigned long long)__float_as_uint(s) << 32) |
            (unsigned long long)(~(unsigned)i);
        g_candKeys[p] = key;
    }
}

// ---------------------------------------------------------------- exact ranking sort
// grid: CAND_CAP/64 blocks x 64 threads (spread over many SMs)
__global__ void k_rank() {
    __shared__ unsigned long long tile[2048];
    int i = blockIdx.x * blockDim.x + threadIdx.x;
    int n = min(g_numCand, CAND_CAP);
    bool active = (i < n);
    unsigned long long my = active ? g_candKeys[i] : 0ULL;
    int rank = 0;
    for (int base = 0; base < n; base += 2048) {
        int cnt = min(2048, n - base);
        for (int j = threadIdx.x; j < cnt; j += blockDim.x)
            tile[j] = g_candKeys[base + j];
        __syncthreads();
        if (active) {
            #pragma unroll 4
            for (int j = 0; j < cnt; j++)
                rank += (tile[j] > my) ? 1 : 0;
        }
        __syncthreads();
    }
    if (active && rank < PRE_NMS) g_sortedKeys[rank] = my;
}

// ---------------------------------------------------------------- gather sorted boxes + valid bits
// grid: 24 blocks x 256 = 6144 threads (covers all VWORDS words)
__global__ void k_gather() {
    int r = blockIdx.x * blockDim.x + threadIdx.x;
    unsigned long long key = (r < PRE_NMS) ? g_sortedKeys[r] : 0ULL;
    int valid = (key != 0ULL);
    if (valid) {
        unsigned idx = ~(unsigned)(key & 0xffffffffULL);
        g_boxesS[r] = g_boxes[idx];
    }
    unsigned bits = __ballot_sync(0xffffffffu, valid);
    if ((threadIdx.x & 31) == 0) {
        int w = r >> 5;
        if (w < VWORDS) g_validbits[w] = bits;
    }
}

// ---------------------------------------------------------------- one-block wavefront NMS
__global__ void k_nms(float* __restrict__ out) {
    __shared__ unsigned int alive[VWORDS];
    __shared__ int s_i;
    __shared__ int s_kcount;
    __shared__ float4 s_box;
    int t = threadIdx.x;
    for (int w = t; w < VWORDS; w += blockDim.x) alive[w] = g_validbits[w];
    if (t == 0) s_kcount = 0;
    __syncthreads();

    int cursor = 0;                     // thread-0 private, monotone
    const int NW = (PRE_NMS + 31) / 32; // 188
    while (true) {
        if (t == 0) {
            int i = -1;
            int w = cursor;
            while (w < NW) {
                unsigned v = alive[w];
                if (v) { i = w * 32 + __ffs(v) - 1; cursor = w; break; }
                w++;
            }
            if (i >= 0) {
                alive[i >> 5] &= ~(1u << (i & 31));
                float4 b = g_boxesS[i];
                s_box = b;
                int k = s_kcount;
                out[k * 5 + 0] = 0.f;
                out[k * 5 + 1] = b.x;
                out[k * 5 + 2] = b.y;
                out[k * 5 + 3] = b.z;
                out[k * 5 + 4] = b.w;
                s_kcount = k + 1;
            }
            s_i = i;
        }
        __syncthreads();
        int i = s_i;
        if (i < 0) break;
        if (s_kcount >= POST_NMS) break;

        float4 bi = s_box;
        float areaI = (bi.z - bi.x) * (bi.w - bi.y);
        for (int j = i + 1 + t; j < PRE_NMS; j += blockDim.x) {
            if ((alive[j >> 5] >> (j & 31)) & 1u) {
                float4 bj = g_boxesS[j];
                float areaJ = (bj.z - bj.x) * (bj.w - bj.y);
                float lx = fmaxf(bi.x, bj.x);
                float ly = fmaxf(bi.y, bj.y);
                float rx = fminf(bi.z, bj.z);
                float ry = fminf(bi.w, bj.w);
                float w_ = fmaxf(rx - lx, 0.f);
                float h_ = fmaxf(ry - ly, 0.f);
                float inter = w_ * h_;
                float iou = inter / (areaI + areaJ - inter);
                if (iou > NMS_THR)
                    atomicAnd(&alive[j >> 5], ~(1u << (j & 31)));
            }
        }
        __syncthreads();
    }
    // all break paths are uniform; zero-fill remaining output rows
    int kc = s_kcount;
    for (int k = kc * 5 + t; k < POST_NMS * 5; k += blockDim.x) out[k] = 0.f;
}

// ---------------------------------------------------------------- launch
extern "C" void kernel_launch(void* const* d_in, const int* in_sizes, int n_in,
                              void* d_out, int out_size) {
    const float* scores  = (const float*)d_in[0];
    const float* deltas  = (const float*)d_in[1];
    const float* im_info = (const float*)d_in[2];
    float* out = (float*)d_out;

    k_zero<<<(PRE_NMS + 255) / 256 + 16, 256>>>();
    k_prep<<<NTOT / 256, 256>>>(scores, deltas, im_info);
    k_thresh<<<1, 1024>>>();
    k_filter<<<NTOT / 256, 256>>>();
    k_rank<<<CAND_CAP / 64, 64>>>();
    k_gather<<<(VWORDS * 32) / 256, 256>>>();
    k_nms<<<1, 1024>>>(out);
}

// round 3
// speedup vs baseline: 2.2206x; 2.2206x over previous
#include <cuda_runtime.h>
#include <cstdint>
#include <math_constants.h>

#define A_NUM 9
#define H_DIM 128
#define W_DIM 192
#define NTOT (H_DIM*W_DIM*A_NUM)   // 221184
#define PRE_NMS 6000
#define POST_NMS 300
#define NBINS 4096
#define CAND_CAP 8192
#define MASK_WORDS ((PRE_NMS+63)/64)   // 94
#define VWORDS (2*MASK_WORDS)          // 188 u32 words
#define NMS_THR 0.7f

__constant__ float c_anchors[A_NUM][4] = {
    {-84.f,  -40.f,  99.f,  55.f},
    {-176.f, -88.f,  191.f, 103.f},
    {-360.f, -184.f, 375.f, 199.f},
    {-56.f,  -56.f,  71.f,  71.f},
    {-120.f, -120.f, 135.f, 135.f},
    {-248.f, -248.f, 263.f, 263.f},
    {-36.f,  -80.f,  51.f,  95.f},
    {-80.f,  -168.f, 95.f,  183.f},
    {-168.f, -344.f, 183.f, 359.f}};

__device__ float4 g_boxes[NTOT];
__device__ float  g_scores[NTOT];
__device__ int    g_hist[NBINS];
__device__ int    g_thr;
__device__ int    g_numCand;
__device__ unsigned long long g_candKeys[CAND_CAP];
__device__ unsigned long long g_sortedKeys[PRE_NMS];
__device__ float4 g_boxesS[PRE_NMS];
__device__ unsigned int g_validbits[VWORDS];
__device__ unsigned long long g_mask[PRE_NMS * MASK_WORDS];

// ---------------------------------------------------------------- zero scratch
__global__ void k_zero() {
    int i = blockIdx.x * blockDim.x + threadIdx.x;
    if (i < NBINS) g_hist[i] = 0;
    if (i < PRE_NMS) g_sortedKeys[i] = 0ULL;
    if (i == 0) g_numCand = 0;
}

// ---------------------------------------------------------------- box decode + histogram
__global__ void k_prep(const float* __restrict__ scores,
                       const float* __restrict__ deltas,
                       const float* __restrict__ im_info) {
    int i = blockIdx.x * blockDim.x + threadIdx.x;
    if (i >= NTOT) return;
    int a = i % A_NUM;
    int pix = i / A_NUM;
    int x = pix % W_DIM;
    int y = pix / W_DIM;
    const int HW = H_DIM * W_DIM;
    int p = y * W_DIM + x;

    float sc = scores[(A_NUM + a) * HW + p];
    float dx = deltas[(4 * a + 0) * HW + p];
    float dy = deltas[(4 * a + 1) * HW + p];
    float dw = deltas[(4 * a + 2) * HW + p];
    float dh = deltas[(4 * a + 3) * HW + p];
    dw = fminf(fmaxf(dw, -10.f), 10.f);
    dh = fminf(fmaxf(dh, -10.f), 10.f);

    float sx = (float)x * 16.f;
    float sy = (float)y * 16.f;
    float ax1 = c_anchors[a][0] + sx;
    float ay1 = c_anchors[a][1] + sy;
    float ax2 = c_anchors[a][2] + sx;
    float ay2 = c_anchors[a][3] + sy;
    float wdt = ax2 - ax1 + 1.f;
    float hgt = ay2 - ay1 + 1.f;
    float cx = ax1 + 0.5f * wdt;
    float cy = ay1 + 0.5f * hgt;

    float pcx = dx * wdt + cx;
    float pcy = dy * hgt + cy;
    float pw = expf(dw) * wdt;
    float ph = expf(dh) * hgt;

    float imH = im_info[0], imW = im_info[1], sc_im = im_info[2];
    float x1 = pcx - 0.5f * pw;
    float y1 = pcy - 0.5f * ph;
    float x2 = pcx + 0.5f * pw;
    float y2 = pcy + 0.5f * ph;
    x1 = fminf(fmaxf(x1, 0.f), imW - 1.f);
    x2 = fminf(fmaxf(x2, 0.f), imW - 1.f);
    y1 = fminf(fmaxf(y1, 0.f), imH - 1.f);
    y2 = fminf(fmaxf(y2, 0.f), imH - 1.f);

    g_boxes[i] = make_float4(x1, y1, x2, y2);
    float minsz = 16.f * sc_im;
    bool valid = (x2 - x1 + 1.f >= minsz) && (y2 - y1 + 1.f >= minsz);
    g_scores[i] = valid ? sc : -CUDART_INF_F;
    if (valid) {
        int bin = (int)(sc * (float)NBINS);
        bin = max(0, min(NBINS - 1, bin));
        atomicAdd(&g_hist[bin], 1);
    }
}

// ---------------------------------------------------------------- histogram threshold
__global__ void k_thresh() {
    __shared__ int sh[NBINS];
    for (int b = threadIdx.x; b < NBINS; b += blockDim.x) sh[b] = g_hist[b];
    __syncthreads();
    if (threadIdx.x == 0) {
        int cum = 0, thr = 0;
        for (int b = NBINS - 1; b >= 0; b--) {
            cum += sh[b];
            if (cum >= PRE_NMS) { thr = b; break; }
        }
        g_thr = thr;
    }
}

// ---------------------------------------------------------------- candidate compaction
__global__ void k_filter() {
    int i = blockIdx.x * blockDim.x + threadIdx.x;
    if (i >= NTOT) return;
    float s = g_scores[i];
    if (!(s >= 0.0f)) return;   // invalid -> -inf
    int bin = (int)(s * (float)NBINS);
    bin = max(0, min(NBINS - 1, bin));
    if (bin < g_thr) return;
    int p = atomicAdd(&g_numCand, 1);
    if (p < CAND_CAP) {
        unsigned long long key =
            ((unsigned long long)__float_as_uint(s) << 32) |
            (unsigned long long)(~(unsigned)i);
        g_candKeys[p] = key;
    }
}

// ---------------------------------------------------------------- exact ranking sort
__global__ void k_rank() {
    __shared__ unsigned long long tile[2048];
    int i = blockIdx.x * blockDim.x + threadIdx.x;
    int n = min(g_numCand, CAND_CAP);
    bool active = (i < n);
    unsigned long long my = active ? g_candKeys[i] : 0ULL;
    int rank = 0;
    for (int base = 0; base < n; base += 2048) {
        int cnt = min(2048, n - base);
        for (int j = threadIdx.x; j < cnt; j += blockDim.x)
            tile[j] = g_candKeys[base + j];
        __syncthreads();
        if (active) {
            #pragma unroll 4
            for (int j = 0; j < cnt; j++)
                rank += (tile[j] > my) ? 1 : 0;
        }
        __syncthreads();
    }
    if (active && rank < PRE_NMS) g_sortedKeys[rank] = my;
}

// ---------------------------------------------------------------- gather sorted boxes + valid bits
__global__ void k_gather() {
    int r = blockIdx.x * blockDim.x + threadIdx.x;
    unsigned long long key = (r < PRE_NMS) ? g_sortedKeys[r] : 0ULL;
    int valid = (key != 0ULL);
    if (r < PRE_NMS) {
        if (valid) {
            unsigned idx = ~(unsigned)(key & 0xffffffffULL);
            g_boxesS[r] = g_boxes[idx];
        } else {
            g_boxesS[r] = make_float4(0.f, 0.f, 0.f, 0.f);
        }
    }
    unsigned bits = __ballot_sync(0xffffffffu, valid);
    if ((threadIdx.x & 31) == 0) {
        int w = r >> 5;
        if (w < VWORDS) g_validbits[w] = bits;
    }
}

// ---------------------------------------------------------------- NMS bitmask (upper triangle)
__global__ void k_mask() {
    int bi = blockIdx.y;   // row block (i)
    int bj = blockIdx.x;   // col block (j)
    if (bj < bi) return;   // only j > i needed
    __shared__ float4 jb[64];
    int jbase = bj * 64;
    int t = threadIdx.x;
    if (jbase + t < PRE_NMS) jb[t] = g_boxesS[jbase + t];
    else jb[t] = make_float4(0.f, 0.f, 0.f, 0.f);
    __syncthreads();

    int i = bi * 64 + t;
    if (i >= PRE_NMS) return;
    float4 b1 = g_boxesS[i];
    float areaI = (b1.z - b1.x) * (b1.w - b1.y);
    unsigned long long bits = 0ULL;
    bool diag = (bi == bj);
    int jmax = min(64, PRE_NMS - jbase);
    #pragma unroll 4
    for (int j = 0; j < jmax; j++) {
        if (diag && jbase + j <= i) continue;
        float4 b2 = jb[j];
        float lx = fmaxf(b1.x, b2.x);
        float ly = fmaxf(b1.y, b2.y);
        float rx = fminf(b1.z, b2.z);
        float ry = fminf(b1.w, b2.w);
        float w = fmaxf(rx - lx, 0.f);
        float h = fmaxf(ry - ly, 0.f);
        float inter = w * h;
        if (inter > 0.f) {
            float areaJ = (b2.z - b2.x) * (b2.w - b2.y);
            float iou = inter / (areaI + areaJ - inter);
            if (iou > NMS_THR) bits |= (1ULL << j);
        }
    }
    g_mask[(size_t)i * MASK_WORDS + bj] = bits;
}

// ---------------------------------------------------------------- word-at-a-time greedy scan (1 warp)
__global__ void k_scan(float* __restrict__ out) {
    __shared__ unsigned long long remv[MASK_WORDS];
    int t = threadIdx.x;
    for (int ww = t; ww < MASK_WORDS; ww += 32) remv[ww] = 0ULL;
    __syncwarp();

    int kcount = 0;   // uniform across warp
    for (int w = 0; w < MASK_WORDS; w++) {
        unsigned long long bits = 0ULL;
        if (t == 0) {
            unsigned long long vw =
                ((unsigned long long)g_validbits[2 * w + 1] << 32) |
                (unsigned long long)g_validbits[2 * w];
            bits = vw & ~remv[w];
        }
        while (true) {
            int i = -1;
            if (t == 0 && bits) i = w * 64 + __ffsll(bits) - 1;
            i = __shfl_sync(0xffffffffu, i, 0);
            if (i < 0) break;            // word exhausted (uniform)
            // keep box i
            if (t == 0) {
                float4 b = g_boxesS[i];
                out[kcount * 5 + 0] = 0.f;
                out[kcount * 5 + 1] = b.x;
                out[kcount * 5 + 2] = b.y;
                out[kcount * 5 + 3] = b.z;
                out[kcount * 5 + 4] = b.w;
            }
            kcount++;
            if (kcount >= POST_NMS) goto done;   // uniform
            {
                const unsigned long long* __restrict__ row =
                    &g_mask[(size_t)i * MASK_WORDS];
                unsigned long long r0 = 0ULL;
                for (int ww = w + t; ww < MASK_WORDS; ww += 32) {
                    unsigned long long rv = row[ww];
                    remv[ww] |= rv;
                    if (ww == w) r0 = rv;     // only thread 0 hits this
                }
                if (t == 0) {
                    bits &= ~(1ULL << (i & 63));
                    bits &= ~r0;              // same-word suppression by i
                }
            }
            __syncwarp();
        }
    }
done:
    // zero-fill remaining rows (kcount uniform)
    for (int k = kcount * 5 + t; k < POST_NMS * 5; k += 32) out[k] = 0.f;
}

// ---------------------------------------------------------------- launch
extern "C" void kernel_launch(void* const* d_in, const int* in_sizes, int n_in,
                              void* d_out, int out_size) {
    const float* scores  = (const float*)d_in[0];
    const float* deltas  = (const float*)d_in[1];
    const float* im_info = (const float*)d_in[2];
    float* out = (float*)d_out;

    k_zero<<<(PRE_NMS + 255) / 256 + 16, 256>>>();
    k_prep<<<NTOT / 256, 256>>>(scores, deltas, im_info);
    k_thresh<<<1, 1024>>>();
    k_filter<<<NTOT / 256, 256>>>();
    k_rank<<<CAND_CAP / 256, 256>>>();
    k_gather<<<(VWORDS * 32 + 255) / 256, 256>>>();
    dim3 mgrid(MASK_WORDS, MASK_WORDS);
    k_mask<<<mgrid, 64>>>();
    k_scan<<<1, 32>>>(out);
}

// round 4
// speedup vs baseline: 4.5196x; 2.0353x over previous
#include <cuda_runtime.h>
#include <cstdint>
#include <math_constants.h>

#define A_NUM 9
#define H_DIM 128
#define W_DIM 192
#define HW (H_DIM*W_DIM)            // 24576
#define NTOT (HW*A_NUM)             // 221184
#define PRE_NMS 6000
#define POST_NMS 300
#define NBINS 4096
#define CAND_CAP 8192
#define MASK_WORDS ((PRE_NMS+63)/64)   // 94
#define VWORDS (2*MASK_WORDS)          // 188 u32
#define NMS_THR 0.7f
#define PREP_BLOCKS (NTOT/256)         // 864
#define MASK_GRID (MASK_WORDS*MASK_WORDS)

__constant__ float c_anchors[A_NUM][4] = {
    {-84.f,  -40.f,  99.f,  55.f},
    {-176.f, -88.f,  191.f, 103.f},
    {-360.f, -184.f, 375.f, 199.f},
    {-56.f,  -56.f,  71.f,  71.f},
    {-120.f, -120.f, 135.f, 135.f},
    {-248.f, -248.f, 263.f, 263.f},
    {-36.f,  -80.f,  51.f,  95.f},
    {-80.f,  -168.f, 95.f,  183.f},
    {-168.f, -344.f, 183.f, 359.f}};

__device__ float4 g_boxes[NTOT];          // [a][p] layout
__device__ float  g_scores[NTOT];         // [a][p] layout
__device__ int    g_hist[NBINS];          // starts zero; re-zeroed each run
__device__ int    g_thr;
__device__ int    g_numCand;
__device__ int    g_done  = 0;
__device__ int    g_done2 = 0;
__device__ unsigned long long g_candKeys[CAND_CAP];
__device__ float4 g_boxesS[PRE_NMS];
__device__ unsigned int g_validbits[VWORDS];
__device__ unsigned long long g_mask[PRE_NMS * MASK_WORDS];

// ============================================================ 1. decode + hist + threshold
__global__ void k_prep(const float* __restrict__ scores,
                       const float* __restrict__ deltas,
                       const float* __restrict__ im_info) {
    int g = blockIdx.x * blockDim.x + threadIdx.x;
    int a = g / HW;
    int p = g - a * HW;
    int x = p % W_DIM;
    int y = p / W_DIM;

    float sc = scores[(A_NUM + a) * HW + p];
    float dx = deltas[(4 * a + 0) * HW + p];
    float dy = deltas[(4 * a + 1) * HW + p];
    float dw = deltas[(4 * a + 2) * HW + p];
    float dh = deltas[(4 * a + 3) * HW + p];
    dw = fminf(fmaxf(dw, -10.f), 10.f);
    dh = fminf(fmaxf(dh, -10.f), 10.f);

    float sx = (float)x * 16.f;
    float sy = (float)y * 16.f;
    float ax1 = c_anchors[a][0] + sx;
    float ay1 = c_anchors[a][1] + sy;
    float ax2 = c_anchors[a][2] + sx;
    float ay2 = c_anchors[a][3] + sy;
    float wdt = ax2 - ax1 + 1.f;
    float hgt = ay2 - ay1 + 1.f;
    float cx = ax1 + 0.5f * wdt;
    float cy = ay1 + 0.5f * hgt;

    float pcx = dx * wdt + cx;
    float pcy = dy * hgt + cy;
    float pw = expf(dw) * wdt;
    float ph = expf(dh) * hgt;

    float imH = __ldg(&im_info[0]), imW = __ldg(&im_info[1]), sc_im = __ldg(&im_info[2]);
    float x1 = pcx - 0.5f * pw;
    float y1 = pcy - 0.5f * ph;
    float x2 = pcx + 0.5f * pw;
    float y2 = pcy + 0.5f * ph;
    x1 = fminf(fmaxf(x1, 0.f), imW - 1.f);
    x2 = fminf(fmaxf(x2, 0.f), imW - 1.f);
    y1 = fminf(fmaxf(y1, 0.f), imH - 1.f);
    y2 = fminf(fmaxf(y2, 0.f), imH - 1.f);

    g_boxes[g] = make_float4(x1, y1, x2, y2);
    float minsz = 16.f * sc_im;
    bool valid = (x2 - x1 + 1.f >= minsz) && (y2 - y1 + 1.f >= minsz);
    g_scores[g] = valid ? sc : -CUDART_INF_F;
    if (valid) {
        int bin = (int)(sc * (float)NBINS);
        bin = max(0, min(NBINS - 1, bin));
        atomicAdd(&g_hist[bin], 1);
    }

    // ---- last-block threshold computation ----
    __shared__ int s_last;
    __shared__ int sh[NBINS];
    __shared__ int csum[256];
    __syncthreads();
    if (threadIdx.x == 0) {
        __threadfence();
        int v = atomicAdd(&g_done, 1);
        s_last = (v == PREP_BLOCKS - 1);
    }
    __syncthreads();
    if (!s_last) return;

    int t = threadIdx.x;
    int base = t * 16;
    int sum = 0;
    #pragma unroll
    for (int k = 0; k < 16; k++) {
        int v = g_hist[base + k];
        sh[base + k] = v;
        g_hist[base + k] = 0;         // re-zero for next run
        sum += v;
    }
    csum[t] = sum;
    if (t < VWORDS) g_validbits[t] = 0u;
    __syncthreads();
    if (t == 0) {
        int cum = 0, thr = 0;
        int c = 255;
        for (; c >= 0; c--) {
            if (cum + csum[c] >= PRE_NMS) break;
            cum += csum[c];
        }
        if (c >= 0) {
            for (int b = c * 16 + 15; b >= c * 16; b--) {
                cum += sh[b];
                if (cum >= PRE_NMS) { thr = b; break; }
            }
        }
        g_thr = thr;
        g_numCand = 0;
        g_done = 0;
    }
}

// ============================================================ 2. candidate compaction
__global__ void k_filter() {
    int g = blockIdx.x * blockDim.x + threadIdx.x;
    float s = g_scores[g];
    if (!(s >= 0.0f)) return;          // invalid -> -inf (scores are in [0,1))
    int bin = (int)(s * (float)NBINS);
    bin = max(0, min(NBINS - 1, bin));
    if (bin < g_thr) return;
    int pos = atomicAdd(&g_numCand, 1);
    if (pos < CAND_CAP) {
        int a = g / HW;
        int p = g - a * HW;
        unsigned i_orig = (unsigned)(p * A_NUM + a);   // reference flatten order
        unsigned long long key =
            ((unsigned long long)__float_as_uint(s) << 32) |
            (unsigned long long)(~i_orig);
        g_candKeys[pos] = key;
    }
}

// ============================================================ 3. ranking sort + gather
__global__ void k_rank() {
    __shared__ unsigned long long tile[2048];
    int i = blockIdx.x * blockDim.x + threadIdx.x;
    int n = min(g_numCand, CAND_CAP);
    bool active = (i < n);
    unsigned long long my = active ? g_candKeys[i] : 0ULL;
    int rank = 0;
    for (int base = 0; base < n; base += 2048) {
        int cnt = min(2048, n - base);
        for (int j = threadIdx.x; j < cnt; j += blockDim.x)
            tile[j] = g_candKeys[base + j];
        __syncthreads();
        if (active) {
            #pragma unroll 8
            for (int j = 0; j < cnt; j++)
                rank += (tile[j] > my) ? 1 : 0;
        }
        __syncthreads();
    }
    if (active && rank < PRE_NMS) {
        unsigned idx = ~(unsigned)(my & 0xffffffffULL);   // i_orig = p*9+a
        int a = (int)(idx % A_NUM);
        int p = (int)(idx / A_NUM);
        g_boxesS[rank] = g_boxes[a * HW + p];
        atomicOr(&g_validbits[rank >> 5], 1u << (rank & 31));
    }
}

// ============================================================ 4. mask + (last block) scan
__global__ void k_mask_scan(float* __restrict__ out) {
    int bi = blockIdx.y;
    int bj = blockIdx.x;
    int t = threadIdx.x;
    __shared__ float4 jb[64];

    bool work = (bj >= bi);
    if (work) {
        int jbase = bj * 64;
        if (jbase + t < PRE_NMS) jb[t] = g_boxesS[jbase + t];
        else jb[t] = make_float4(0.f, 0.f, 0.f, 0.f);
    }
    __syncthreads();
    if (work) {
        int i = bi * 64 + t;
        if (i < PRE_NMS) {
            int jbase = bj * 64;
            float4 b1 = g_boxesS[i];
            unsigned long long bits = 0ULL;
            bool diag = (bi == bj);
            int jmax = min(64, PRE_NMS - jbase);
            #pragma unroll 4
            for (int j = 0; j < jmax; j++) {
                if (diag && jbase + j <= i) continue;
                float4 b2 = jb[j];
                float lx = fmaxf(b1.x, b2.x);
                float ly = fmaxf(b1.y, b2.y);
                float rx = fminf(b1.z, b2.z);
                float ry = fminf(b1.w, b2.w);
                float w = fmaxf(rx - lx, 0.f);
                float h = fmaxf(ry - ly, 0.f);
                float inter = w * h;
                if (inter > 0.f) {
                    float areaI = (b1.z - b1.x) * (b1.w - b1.y);
                    float areaJ = (b2.z - b2.x) * (b2.w - b2.y);
                    float iou = inter / (areaI + areaJ - inter);
                    if (iou > NMS_THR) bits |= (1ULL << j);
                }
            }
            g_mask[(size_t)i * MASK_WORDS + bj] = bits;
        }
    }

    // ---- completion protocol ----
    __shared__ int s_last;
    __syncthreads();
    if (t == 0) {
        __threadfence();
        int v = atomicAdd(&g_done2, 1);
        s_last = (v == MASK_GRID - 1);
    }
    __syncthreads();
    if (!s_last) return;
    if (t == 0) g_done2 = 0;
    if (t >= 32) return;

    // ---- greedy NMS scan on warp 0 of the last block ----
    __shared__ unsigned long long remv[MASK_WORDS];
    __shared__ unsigned long long vbits[MASK_WORDS];
    __shared__ unsigned long long colbuf[2][64];
    __shared__ float4 colbox[2][64];
    __shared__ int s_kept[64];
    __shared__ int s_nk, s_kc, s_stop;

    for (int ww = t; ww < MASK_WORDS; ww += 32) {
        remv[ww] = 0ULL;
        vbits[ww] = ((unsigned long long)g_validbits[2 * ww + 1] << 32) |
                    (unsigned long long)g_validbits[2 * ww];
    }
    for (int j = t; j < 64; j += 32) {
        colbuf[0][j] = g_mask[(size_t)j * MASK_WORDS + 0];
        colbox[0][j] = g_boxesS[j];
    }
    if (t == 0) { s_kc = 0; s_stop = 0; }
    __syncwarp();

    int kcount = 0;
    for (int w = 0; w < MASK_WORDS; w++) {
        int cur = w & 1, nxt = cur ^ 1;
        // prefetch next word's diagonal column + boxes
        if (w + 1 < MASK_WORDS) {
            int nb = (w + 1) * 64;
            for (int j = t; j < 64; j += 32) {
                int r = nb + j;
                if (r < PRE_NMS) {
                    colbuf[nxt][j] = __ldg(&g_mask[(size_t)r * MASK_WORDS + (w + 1)]);
                    colbox[nxt][j] = g_boxesS[r];
                }
            }
        }
        if (t == 0) {
            unsigned long long bits = vbits[w] & ~remv[w];
            int nk = 0;
            while (bits) {
                int ib = __ffsll(bits) - 1;
                bits &= bits - 1;
                float4 b = colbox[cur][ib];
                out[kcount * 5 + 0] = 0.f;
                out[kcount * 5 + 1] = b.x;
                out[kcount * 5 + 2] = b.y;
                out[kcount * 5 + 3] = b.z;
                out[kcount * 5 + 4] = b.w;
                s_kept[nk++] = w * 64 + ib;
                kcount++;
                if (kcount >= POST_NMS) { s_stop = 1; break; }
                bits &= ~colbuf[cur][ib];     // intra-word suppression
            }
            s_nk = nk;
            s_kc = kcount;
        }
        __syncwarp();
        if (s_stop) break;
        int nk = s_nk;
        if (nk > 0 && t > 0) {
            // lanes 1..31 OR kept rows into remv for words > w (31*3 >= 93)
            for (int ww = w + t; ww < MASK_WORDS; ww += 31) {
                unsigned long long acc = 0ULL;
                for (int k = 0; k < nk; k++)
                    acc |= __ldg(&g_mask[(size_t)s_kept[k] * MASK_WORDS + ww]);
                remv[ww] |= acc;
            }
        }
        __syncwarp();
    }
    __syncwarp();
    int kc = s_kc;
    for (int x = kc * 5 + t; x < POST_NMS * 5; x += 32) out[x] = 0.f;
}

// ============================================================ launch
extern "C" void kernel_launch(void* const* d_in, const int* in_sizes, int n_in,
                              void* d_out, int out_size) {
    const float* scores  = (const float*)d_in[0];
    const float* deltas  = (const float*)d_in[1];
    const float* im_info = (const float*)d_in[2];
    float* out = (float*)d_out;

    k_prep<<<PREP_BLOCKS, 256>>>(scores, deltas, im_info);
    k_filter<<<PREP_BLOCKS, 256>>>();
    k_rank<<<CAND_CAP / 64, 64>>>();
    dim3 mgrid(MASK_WORDS, MASK_WORDS);
    k_mask_scan<<<mgrid, 64>>>(out);
}